// round 4
// baseline (speedup 1.0000x reference)
#include <cuda_runtime.h>
#include <math.h>

#define N_NODES 40962
#define N_EDGES 245760
#define KG 10
#define GMM_EPS 1e-15f
#define K1 704      // 640 (agg1) + 64 (x row -> root1)
#define K2 1408     // 640 (agg2) + 64 (h) + 640 (aggs) + 64 (x)

// ---------------- scratch (device globals; no runtime allocation) -------------
__device__ int   d_cnt[N_NODES];
__device__ int   d_cur[N_NODES];
__device__ int   d_offs[N_NODES + 1];
__device__ float d_dinv[N_NODES];
__device__ int2  d_se[N_EDGES];                  // (src, orig edge id), dst-sorted
__device__ float d_t1[(size_t)N_NODES * K1];
__device__ float d_t2[(size_t)N_NODES * K2];
__device__ float d_h [(size_t)N_NODES * 64];
__device__ float d_B1[K1 * 64];
__device__ float d_B2[K2 * 128];
__device__ float d_bias2[128];

// ---------------- prep kernels ------------------------------------------------
__global__ void zero_cnt() {
    int i = blockIdx.x * blockDim.x + threadIdx.x;
    if (i < N_NODES) { d_cnt[i] = 0; d_cur[i] = 0; }
}

__global__ void hist_dst(const int* __restrict__ ei) {
    int e = blockIdx.x * blockDim.x + threadIdx.x;
    if (e < N_EDGES) atomicAdd(&d_cnt[ei[N_EDGES + e]], 1);
}

// single block, register-serial scan: each thread owns 41 contiguous counts
#define SCAN_C 41
__global__ __launch_bounds__(1024) void scan_deg() {
    __shared__ int sh[32];
    int t = threadIdx.x, lane = t & 31, wid = t >> 5;
    int base = t * SCAN_C;
    int vals[SCAN_C];
    int sum = 0;
    #pragma unroll
    for (int j = 0; j < SCAN_C; ++j) {
        int i = base + j;
        int v = (i < N_NODES) ? d_cnt[i] : 0;
        vals[j] = sum;
        sum += v;
        if (i < N_NODES) d_dinv[i] = 1.0f / (float)max(v, 1);
    }
    // block exclusive scan of per-thread sums
    int s = sum;
    #pragma unroll
    for (int off = 1; off < 32; off <<= 1) {
        int n = __shfl_up_sync(0xffffffffu, s, off);
        if (lane >= off) s += n;
    }
    if (lane == 31) sh[wid] = s;
    __syncthreads();
    if (wid == 0) {
        int w = sh[lane];
        #pragma unroll
        for (int off = 1; off < 32; off <<= 1) {
            int n = __shfl_up_sync(0xffffffffu, w, off);
            if (lane >= off) w += n;
        }
        sh[lane] = w;
    }
    __syncthreads();
    int excl = s - sum + (wid > 0 ? sh[wid - 1] : 0);
    #pragma unroll
    for (int j = 0; j < SCAN_C; ++j) {
        int i = base + j;
        if (i < N_NODES) d_offs[i] = excl + vals[j];
    }
    if (t == 0) d_offs[N_NODES] = N_EDGES;
}

// weave both big B matrices + combined bias
__global__ void bweave(const float* __restrict__ g1, const float* __restrict__ root1,
                       const float* __restrict__ g2, const float* __restrict__ root2,
                       const float* __restrict__ gs, const float* __restrict__ roots,
                       const float* __restrict__ b2, const float* __restrict__ bs) {
    int idx = blockIdx.x * blockDim.x + threadIdx.x;
    if (idx < 128) d_bias2[idx] = b2[idx] + bs[idx];
    if (idx < K1 * 64) {
        int r = idx >> 6, c = idx & 63;
        float v;
        if (r < 640) { int k = r >> 6, cin = r & 63; v = g1[cin * 640 + k * 64 + c]; }
        else         { v = root1[(r - 640) * 64 + c]; }
        d_B1[idx] = v;
    }
    if (idx < K2 * 128) {
        int r = idx >> 7, c = idx & 127;
        float v;
        if (r < 640)       { int k = r >> 6, cin = r & 63; v = g2[cin * 1280 + k * 128 + c]; }
        else if (r < 704)  { v = root2[(r - 640) * 128 + c]; }
        else if (r < 1344) { int rr = r - 704; int k = rr >> 6, cin = rr & 63; v = gs[cin * 1280 + k * 128 + c]; }
        else               { v = roots[(r - 1344) * 128 + c]; }
        d_B2[idx] = v;
    }
}

// dst-sort scatter: just (src, edge-id)
__global__ void scatter_idx(const int* __restrict__ ei) {
    int e = blockIdx.x * blockDim.x + threadIdx.x;
    if (e >= N_EDGES) return;
    int src = ei[e];
    int dst = ei[N_EDGES + e];
    int pos = d_offs[dst] + atomicAdd(&d_cur[dst], 1);
    d_se[pos] = make_int2(src, e);
}

// ---------------- t-builds (warp per dst node, inline gaussians) --------------
__global__ __launch_bounds__(256) void tbuild1(
    const float* __restrict__ x, const float* __restrict__ pseudo,
    const float* __restrict__ mu, const float* __restrict__ sg)
{
    int gw = (blockIdx.x * blockDim.x + threadIdx.x) >> 5;
    int lane = threadIdx.x & 31;
    if (gw >= N_NODES) return;

    // per-lane gaussian params (lanes 0..9)
    float m0 = 0.f, m1 = 0.f, i0 = 0.f, i1 = 0.f;
    if (lane < KG) {
        m0 = mu[2 * lane]; m1 = mu[2 * lane + 1];
        float s0 = sg[2 * lane], s1 = sg[2 * lane + 1];
        i0 = -0.5f / (GMM_EPS + s0 * s0);
        i1 = -0.5f / (GMM_EPS + s1 * s1);
    }

    int beg = d_offs[gw], end = d_offs[gw + 1];
    float dinv = d_dinv[gw];
    float a[KG][2];
    #pragma unroll
    for (int k = 0; k < KG; ++k) { a[k][0] = 0.f; a[k][1] = 0.f; }

    int2 se_next = (beg < end) ? d_se[beg] : make_int2(0, 0);
    for (int e = beg; e < end; ++e) {
        int2 se = se_next;
        if (e + 1 < end) se_next = d_se[e + 1];
        float2 p = ((const float2*)pseudo)[se.y];
        float wv = 0.f;
        if (lane < KG) {
            float dx = p.x - m0, dy = p.y - m1;
            wv = __expf(dx * dx * i0 + dy * dy * i1);
        }
        float x0 = x[(size_t)se.x * 64 + lane];
        float x1 = x[(size_t)se.x * 64 + 32 + lane];
        #pragma unroll
        for (int k = 0; k < KG; ++k) {
            float w = __shfl_sync(0xffffffffu, wv, k);
            a[k][0] = fmaf(w, x0, a[k][0]);
            a[k][1] = fmaf(w, x1, a[k][1]);
        }
    }
    float* tr = d_t1 + (size_t)gw * K1;
    #pragma unroll
    for (int k = 0; k < KG; ++k) {
        tr[k * 64 + lane]      = a[k][0] * dinv;
        tr[k * 64 + 32 + lane] = a[k][1] * dinv;
    }
    tr[640 + lane]      = x[(size_t)gw * 64 + lane];
    tr[640 + 32 + lane] = x[(size_t)gw * 64 + 32 + lane];
}

__global__ __launch_bounds__(256) void tbuild2(
    const float* __restrict__ x, const float* __restrict__ pseudo,
    const float* __restrict__ mu2, const float* __restrict__ sg2,
    const float* __restrict__ mus, const float* __restrict__ sgs)
{
    int gw = (blockIdx.x * blockDim.x + threadIdx.x) >> 5;
    int lane = threadIdx.x & 31;
    if (gw >= N_NODES) return;

    // lanes 0..9: conv2 params; lanes 10..19: shortcut params
    float m0 = 0.f, m1 = 0.f, i0 = 0.f, i1 = 0.f;
    if (lane < KG) {
        m0 = mu2[2 * lane]; m1 = mu2[2 * lane + 1];
        float s0 = sg2[2 * lane], s1 = sg2[2 * lane + 1];
        i0 = -0.5f / (GMM_EPS + s0 * s0);
        i1 = -0.5f / (GMM_EPS + s1 * s1);
    } else if (lane < 2 * KG) {
        int k = lane - KG;
        m0 = mus[2 * k]; m1 = mus[2 * k + 1];
        float s0 = sgs[2 * k], s1 = sgs[2 * k + 1];
        i0 = -0.5f / (GMM_EPS + s0 * s0);
        i1 = -0.5f / (GMM_EPS + s1 * s1);
    }

    int beg = d_offs[gw], end = d_offs[gw + 1];
    float dinv = d_dinv[gw];
    float a2[KG][2], as_[KG][2];
    #pragma unroll
    for (int k = 0; k < KG; ++k) { a2[k][0]=0.f; a2[k][1]=0.f; as_[k][0]=0.f; as_[k][1]=0.f; }

    int2 se_next = (beg < end) ? d_se[beg] : make_int2(0, 0);
    for (int e = beg; e < end; ++e) {
        int2 se = se_next;
        if (e + 1 < end) se_next = d_se[e + 1];
        float2 p = ((const float2*)pseudo)[se.y];
        float wv = 0.f;
        if (lane < 2 * KG) {
            float dx = p.x - m0, dy = p.y - m1;
            wv = __expf(dx * dx * i0 + dy * dy * i1);
        }
        float h0 = d_h[(size_t)se.x * 64 + lane];
        float h1 = d_h[(size_t)se.x * 64 + 32 + lane];
        float x0 = x[(size_t)se.x * 64 + lane];
        float x1 = x[(size_t)se.x * 64 + 32 + lane];
        #pragma unroll
        for (int k = 0; k < KG; ++k) {
            float w2 = __shfl_sync(0xffffffffu, wv, k);
            float ws = __shfl_sync(0xffffffffu, wv, KG + k);
            a2[k][0]  = fmaf(w2, h0, a2[k][0]);
            a2[k][1]  = fmaf(w2, h1, a2[k][1]);
            as_[k][0] = fmaf(ws, x0, as_[k][0]);
            as_[k][1] = fmaf(ws, x1, as_[k][1]);
        }
    }
    float* tr = d_t2 + (size_t)gw * K2;
    #pragma unroll
    for (int k = 0; k < KG; ++k) {
        tr[k * 64 + lane]            = a2[k][0] * dinv;
        tr[k * 64 + 32 + lane]       = a2[k][1] * dinv;
        tr[704 + k * 64 + lane]      = as_[k][0] * dinv;
        tr[704 + k * 64 + 32 + lane] = as_[k][1] * dinv;
    }
    tr[640 + lane]       = d_h[(size_t)gw * 64 + lane];
    tr[640 + 32 + lane]  = d_h[(size_t)gw * 64 + 32 + lane];
    tr[1344 + lane]      = x[(size_t)gw * 64 + lane];
    tr[1344 + 32 + lane] = x[(size_t)gw * 64 + 32 + lane];
}

// ---------------- tf32 helpers ------------------------------------------------
__device__ __forceinline__ unsigned f2tf32(float x) {
    unsigned r;
    asm("cvt.rna.tf32.f32 %0, %1;" : "=r"(r) : "f"(x));
    return r;
}
__device__ __forceinline__ unsigned fu(float x) { return __float_as_uint(x); }

// ---------------- GEMM A: BM=64, BN=64 (layer 1, N=64) ------------------------
__global__ __launch_bounds__(256) void gemm64(
    const float* __restrict__ A, const float* __restrict__ B,
    float* __restrict__ C, int M, int N, int K, const float* __restrict__ bias)
{
    __shared__ float As[64][68];
    __shared__ float Bs[64][72];
    const int tid = threadIdx.x;
    const int bm = blockIdx.y * 64;
    const int bn = blockIdx.x * 64;
    const int wid = tid >> 5, l = tid & 31;
    const int wr = wid & 3, wc = wid >> 2;
    const int tg = l >> 2, ti = l & 3;

    float acc[4][4] = {};
    for (int kc = 0; kc < K; kc += 64) {
        {
            int row = tid >> 2, cq = (tid & 3) * 16;
            bool av = (bm + row) < M;
            const float* ap = A + (size_t)(bm + row) * K + kc + cq;
            #pragma unroll
            for (int j = 0; j < 4; ++j) {
                float4 v = av ? *(const float4*)(ap + 4 * j) : make_float4(0.f,0.f,0.f,0.f);
                As[row][cq+4*j+0] = __uint_as_float(f2tf32(v.x));
                As[row][cq+4*j+1] = __uint_as_float(f2tf32(v.y));
                As[row][cq+4*j+2] = __uint_as_float(f2tf32(v.z));
                As[row][cq+4*j+3] = __uint_as_float(f2tf32(v.w));
            }
        }
        {
            int k = tid >> 2, nq = (tid & 3) * 16;
            const float* bp = B + (size_t)(kc + k) * N + bn + nq;
            #pragma unroll
            for (int j = 0; j < 4; ++j) {
                float4 v = *(const float4*)(bp + 4 * j);
                Bs[k][nq+4*j+0] = __uint_as_float(f2tf32(v.x));
                Bs[k][nq+4*j+1] = __uint_as_float(f2tf32(v.y));
                Bs[k][nq+4*j+2] = __uint_as_float(f2tf32(v.z));
                Bs[k][nq+4*j+3] = __uint_as_float(f2tf32(v.w));
            }
        }
        __syncthreads();
        #pragma unroll
        for (int ks = 0; ks < 8; ++ks) {
            int c0 = ks * 8 + ti;
            unsigned a0 = fu(As[wr*16+tg  ][c0  ]);
            unsigned a1 = fu(As[wr*16+tg+8][c0  ]);
            unsigned a2 = fu(As[wr*16+tg  ][c0+4]);
            unsigned a3 = fu(As[wr*16+tg+8][c0+4]);
            #pragma unroll
            for (int nt = 0; nt < 4; ++nt) {
                int bc = wc * 32 + nt * 8 + tg;
                unsigned b0 = fu(Bs[ks*8+ti  ][bc]);
                unsigned b1 = fu(Bs[ks*8+ti+4][bc]);
                asm volatile(
                    "mma.sync.aligned.m16n8k8.row.col.f32.tf32.tf32.f32 "
                    "{%0,%1,%2,%3}, {%4,%5,%6,%7}, {%8,%9}, {%0,%1,%2,%3};"
                    : "+f"(acc[nt][0]), "+f"(acc[nt][1]),
                      "+f"(acc[nt][2]), "+f"(acc[nt][3])
                    : "r"(a0), "r"(a1), "r"(a2), "r"(a3), "r"(b0), "r"(b1));
            }
        }
        __syncthreads();
    }
    #pragma unroll
    for (int nt = 0; nt < 4; ++nt) {
        int col = bn + wc * 32 + nt * 8 + 2 * ti;
        float bv0 = bias[col], bv1 = bias[col + 1];
        int r0 = bm + wr * 16 + tg, r1 = r0 + 8;
        if (r0 < M)
            *(float2*)(C + (size_t)r0 * N + col) =
                make_float2(fmaxf(acc[nt][0] + bv0, 0.f), fmaxf(acc[nt][1] + bv1, 0.f));
        if (r1 < M)
            *(float2*)(C + (size_t)r1 * N + col) =
                make_float2(fmaxf(acc[nt][2] + bv0, 0.f), fmaxf(acc[nt][3] + bv1, 0.f));
    }
}

// ---------------- GEMM B: BM=64, BN=128 (layer 2), 32x32 warp tiles -----------
__global__ __launch_bounds__(256) void gemm128(
    const float* __restrict__ A, const float* __restrict__ B,
    float* __restrict__ C, int M, int K, const float* __restrict__ bias)
{
    __shared__ float As[64][68];
    __shared__ float Bs[64][136];
    const int tid = threadIdx.x;
    const int bm = blockIdx.x * 64;
    const int wid = tid >> 5, l = tid & 31;
    const int wr = wid & 1;        // 2 m-warps: rows wr*32..+31
    const int wc = wid >> 1;       // 4 n-warps: cols wc*32..+31
    const int tg = l >> 2, ti = l & 3;

    float acc[2][4][4] = {};
    for (int kc = 0; kc < K; kc += 64) {
        {
            int row = tid >> 2, cq = (tid & 3) * 16;
            bool av = (bm + row) < M;
            const float* ap = A + (size_t)(bm + row) * K + kc + cq;
            #pragma unroll
            for (int j = 0; j < 4; ++j) {
                float4 v = av ? *(const float4*)(ap + 4 * j) : make_float4(0.f,0.f,0.f,0.f);
                As[row][cq+4*j+0] = __uint_as_float(f2tf32(v.x));
                As[row][cq+4*j+1] = __uint_as_float(f2tf32(v.y));
                As[row][cq+4*j+2] = __uint_as_float(f2tf32(v.z));
                As[row][cq+4*j+3] = __uint_as_float(f2tf32(v.w));
            }
        }
        {
            int k = tid >> 2, nq = (tid & 3) * 32;     // 8 float4 per thread
            const float* bp = B + (size_t)(kc + k) * 128 + nq;
            #pragma unroll
            for (int j = 0; j < 8; ++j) {
                float4 v = *(const float4*)(bp + 4 * j);
                Bs[k][nq+4*j+0] = __uint_as_float(f2tf32(v.x));
                Bs[k][nq+4*j+1] = __uint_as_float(f2tf32(v.y));
                Bs[k][nq+4*j+2] = __uint_as_float(f2tf32(v.z));
                Bs[k][nq+4*j+3] = __uint_as_float(f2tf32(v.w));
            }
        }
        __syncthreads();
        #pragma unroll
        for (int ks = 0; ks < 8; ++ks) {
            int c0 = ks * 8 + ti;
            unsigned a[2][4];
            #pragma unroll
            for (int mt = 0; mt < 2; ++mt) {
                int r0 = wr * 32 + mt * 16 + tg;
                a[mt][0] = fu(As[r0  ][c0  ]);
                a[mt][1] = fu(As[r0+8][c0  ]);
                a[mt][2] = fu(As[r0  ][c0+4]);
                a[mt][3] = fu(As[r0+8][c0+4]);
            }
            #pragma unroll
            for (int nt = 0; nt < 4; ++nt) {
                int bc = wc * 32 + nt * 8 + tg;
                unsigned b0 = fu(Bs[ks*8+ti  ][bc]);
                unsigned b1 = fu(Bs[ks*8+ti+4][bc]);
                #pragma unroll
                for (int mt = 0; mt < 2; ++mt) {
                    asm volatile(
                        "mma.sync.aligned.m16n8k8.row.col.f32.tf32.tf32.f32 "
                        "{%0,%1,%2,%3}, {%4,%5,%6,%7}, {%8,%9}, {%0,%1,%2,%3};"
                        : "+f"(acc[mt][nt][0]), "+f"(acc[mt][nt][1]),
                          "+f"(acc[mt][nt][2]), "+f"(acc[mt][nt][3])
                        : "r"(a[mt][0]), "r"(a[mt][1]), "r"(a[mt][2]), "r"(a[mt][3]),
                          "r"(b0), "r"(b1));
                }
            }
        }
        __syncthreads();
    }
    #pragma unroll
    for (int mt = 0; mt < 2; ++mt) {
        #pragma unroll
        for (int nt = 0; nt < 4; ++nt) {
            int col = wc * 32 + nt * 8 + 2 * ti;
            float bv0 = bias[col], bv1 = bias[col + 1];
            int r0 = bm + wr * 32 + mt * 16 + tg, r1 = r0 + 8;
            if (r0 < M)
                *(float2*)(C + (size_t)r0 * 128 + col) =
                    make_float2(fmaxf(acc[mt][nt][0] + bv0, 0.f), fmaxf(acc[mt][nt][1] + bv1, 0.f));
            if (r1 < M)
                *(float2*)(C + (size_t)r1 * 128 + col) =
                    make_float2(fmaxf(acc[mt][nt][2] + bv0, 0.f), fmaxf(acc[mt][nt][3] + bv1, 0.f));
        }
    }
}

// ---------------- launch ------------------------------------------------------
extern "C" void kernel_launch(void* const* d_in, const int* in_sizes, int n_in,
                              void* d_out, int out_size) {
    const float* x      = (const float*)d_in[0];
    const int*   ei     = (const int*)  d_in[1];
    const float* pseudo = (const float*)d_in[2];
    const float* g1     = (const float*)d_in[3];
    const float* mu1    = (const float*)d_in[4];
    const float* sigma1 = (const float*)d_in[5];
    const float* root1  = (const float*)d_in[6];
    const float* b1     = (const float*)d_in[7];
    const float* g2     = (const float*)d_in[8];
    const float* mu2    = (const float*)d_in[9];
    const float* sigma2 = (const float*)d_in[10];
    const float* root2  = (const float*)d_in[11];
    const float* b2     = (const float*)d_in[12];
    const float* gs     = (const float*)d_in[13];
    const float* mus    = (const float*)d_in[14];
    const float* sigmas = (const float*)d_in[15];
    const float* roots  = (const float*)d_in[16];
    const float* bs     = (const float*)d_in[17];
    float* out = (float*)d_out;

    float *t1p, *t2p, *hp, *B1p, *B2p, *bias2p;
    cudaGetSymbolAddress((void**)&t1p, d_t1);
    cudaGetSymbolAddress((void**)&t2p, d_t2);
    cudaGetSymbolAddress((void**)&hp,  d_h);
    cudaGetSymbolAddress((void**)&B1p, d_B1);
    cudaGetSymbolAddress((void**)&B2p, d_B2);
    cudaGetSymbolAddress((void**)&bias2p, d_bias2);

    const int MT = (N_NODES + 63) / 64;        // 641 row tiles
    const int EW = (N_EDGES + 255) / 256;      // edge blocks
    const int NW = (N_NODES * 32 + 255) / 256; // warp-per-node grid

    // CSR build + weight weave
    zero_cnt<<<(N_NODES + 255) / 256, 256>>>();
    hist_dst<<<EW, 256>>>(ei);
    scan_deg<<<1, 1024>>>();
    bweave<<<(K2 * 128 + 255) / 256, 256>>>(g1, root1, g2, root2, gs, roots, b2, bs);
    scatter_idx<<<EW, 256>>>(ei);

    // conv1: t1 = [mean-agg(x) | x], h = relu(t1 @ B1 + b1)
    tbuild1<<<NW, 256>>>(x, pseudo, mu1, sigma1);
    gemm64<<<dim3(1, MT), 256>>>(t1p, B1p, hp, N_NODES, 64, K1, b1);

    // conv2 + shortcut: t2 = [agg(h) | h | agg(x) | x], out = relu(t2 @ B2 + bias)
    tbuild2<<<NW, 256>>>(x, pseudo, mu2, sigma2, mus, sigmas);
    gemm128<<<MT, 256>>>(t2p, B2p, out, N_NODES, K2, bias2p);
}